// round 5
// baseline (speedup 1.0000x reference)
#include <cuda_runtime.h>

// Problem constants
#define BATCH   2
#define SEQ     2048
#define DMODEL  1024
#define NHEAD   16
#define HDIM    64
#define MTOT    (BATCH * SEQ)   // 4096

// Scratch (device globals — no allocation allowed)
__device__ float g_q[BATCH * NHEAD * SEQ * HDIM];  // [b,h,s,d]
__device__ float g_k[BATCH * NHEAD * SEQ * HDIM];
__device__ float g_v[BATCH * NHEAD * SEQ * HDIM];
__device__ float g_y[MTOT * DMODEL];               // attention output, [b*s, d]

// ----------------------------------------------------------------------------
// GEMM: C[m,n] = sum_k A[m,k] * W[n,k]   (i.e. A @ W^T), M=4096, N=1024, K=1024
// 128x128 block tile, K-step 8, 256 threads, 8x8 per-thread microtile.
// MODE 0: A = x, W selected by blockIdx.z from {wq,wk,wv}; output scattered
//         into g_q/g_k/g_v with [b,h,s,d] layout.
// MODE 1: A = g_y, W = wo; output = Out[m,n] + bias[n].
// ----------------------------------------------------------------------------
template <int MODE>
__global__ __launch_bounds__(256)
void gemm128(const float* __restrict__ Ain,
             const float* __restrict__ W0,
             const float* __restrict__ W1,
             const float* __restrict__ W2,
             const float* __restrict__ bias,
             float* __restrict__ Out)
{
    __shared__ float As[8][129];   // [k][m], padded
    __shared__ float Bs[8][129];   // [k][n], padded

    const int K = DMODEL;
    const float* A = (MODE == 0) ? Ain : g_y;
    const float* W;
    if (MODE == 0) {
        int z = blockIdx.z;
        W = (z == 0) ? W0 : ((z == 1) ? W1 : W2);
    } else {
        W = W0;
    }

    const int m0 = blockIdx.y * 128;
    const int n0 = blockIdx.x * 128;
    const int tid = threadIdx.x;
    const int tx = tid & 15;        // 0..15 -> output cols n0 + tx*8 + j
    const int ty = tid >> 4;        // 0..15 -> output rows m0 + ty*8 + i
    const int lm = tid >> 1;        // 0..127 loader row
    const int lk = (tid & 1) * 4;   // 0 or 4 loader k-offset

    const float* aptr = A + (size_t)(m0 + lm) * K + lk;
    const float* bptr = W + (size_t)(n0 + lm) * K + lk;

    float acc[8][8];
    #pragma unroll
    for (int i = 0; i < 8; i++)
        #pragma unroll
        for (int j = 0; j < 8; j++) acc[i][j] = 0.0f;

    // Preload tile 0
    float4 ra = *(const float4*)aptr;
    float4 rb = *(const float4*)bptr;
    As[lk + 0][lm] = ra.x; As[lk + 1][lm] = ra.y; As[lk + 2][lm] = ra.z; As[lk + 3][lm] = ra.w;
    Bs[lk + 0][lm] = rb.x; Bs[lk + 1][lm] = rb.y; Bs[lk + 2][lm] = rb.z; Bs[lk + 3][lm] = rb.w;
    __syncthreads();

    for (int kt = 8; kt <= K; kt += 8) {
        const bool more = (kt < K);
        if (more) {
            ra = *(const float4*)(aptr + kt);
            rb = *(const float4*)(bptr + kt);
        }
        #pragma unroll
        for (int kk = 0; kk < 8; kk++) {
            float a[8], b[8];
            #pragma unroll
            for (int i = 0; i < 8; i++) a[i] = As[kk][ty * 8 + i];
            #pragma unroll
            for (int j = 0; j < 8; j++) b[j] = Bs[kk][tx * 8 + j];
            #pragma unroll
            for (int i = 0; i < 8; i++)
                #pragma unroll
                for (int j = 0; j < 8; j++)
                    acc[i][j] += a[i] * b[j];
        }
        __syncthreads();
        if (more) {
            As[lk + 0][lm] = ra.x; As[lk + 1][lm] = ra.y; As[lk + 2][lm] = ra.z; As[lk + 3][lm] = ra.w;
            Bs[lk + 0][lm] = rb.x; Bs[lk + 1][lm] = rb.y; Bs[lk + 2][lm] = rb.z; Bs[lk + 3][lm] = rb.w;
        }
        __syncthreads();
    }

    if (MODE == 0) {
        const int z = blockIdx.z;
        float* dst = (z == 0) ? g_q : ((z == 1) ? g_k : g_v);
        #pragma unroll
        for (int i = 0; i < 8; i++) {
            const int m = m0 + ty * 8 + i;
            const int b = m >> 11;        // / 2048
            const int s = m & (SEQ - 1);
            #pragma unroll
            for (int jj = 0; jj < 8; jj += 4) {
                const int n = n0 + tx * 8 + jj;
                const int h = n >> 6;     // / 64
                const int d = n & (HDIM - 1);
                float4 v = make_float4(acc[i][jj], acc[i][jj + 1], acc[i][jj + 2], acc[i][jj + 3]);
                *(float4*)&dst[(((size_t)(b * NHEAD + h) * SEQ) + s) * HDIM + d] = v;
            }
        }
    } else {
        float bj[8];
        #pragma unroll
        for (int j = 0; j < 8; j++) bj[j] = bias[n0 + tx * 8 + j];
        #pragma unroll
        for (int i = 0; i < 8; i++) {
            const int m = m0 + ty * 8 + i;
            #pragma unroll
            for (int jj = 0; jj < 8; jj += 4) {
                const int n = n0 + tx * 8 + jj;
                float4 v = make_float4(acc[i][jj] + bj[jj], acc[i][jj + 1] + bj[jj + 1],
                                       acc[i][jj + 2] + bj[jj + 2], acc[i][jj + 3] + bj[jj + 3]);
                *(float4*)&Out[(size_t)m * DMODEL + n] = v;
            }
        }
    }
}

// ----------------------------------------------------------------------------
// Flash attention: one block = 64 queries of one (b,h). Online softmax over
// 32 KV tiles of 64. 256 threads, each owns a 4x4 microtile (rows = 4*ty+i,
// cols = 4*tx+j) for both the 64x64 score tile and the 64x64 (Dh) out tile.
// Smem: Qs[64][65] (Q pre-scaled), KP[64][65] (K tile, then reused for P),
// Vs[64][64]. Total 49,664 B dynamic.
// ----------------------------------------------------------------------------
__global__ __launch_bounds__(256)
void attn_kernel()
{
    extern __shared__ float sm[];
    float* Qs = sm;                  // [64][65]
    float* KP = sm + 64 * 65;        // [64][65]
    float* Vs = sm + 2 * 64 * 65;    // [64][64]

    const int qt = blockIdx.x;       // query tile (32)
    const int bh = blockIdx.y;       // b*NHEAD + h (32)
    const float* qp = g_q + ((size_t)bh * SEQ + qt * 64) * HDIM;
    const float* kp = g_k + (size_t)bh * SEQ * HDIM;
    const float* vp = g_v + (size_t)bh * SEQ * HDIM;

    const int tid = threadIdx.x;
    const int tx = tid & 15;
    const int ty = tid >> 4;
    const float scale = 0.125f;      // 1/sqrt(64)

    // Load Q tile (pre-scaled by softmax scale)
    for (int f = tid; f < 1024; f += 256) {
        const int row = f >> 4;
        const int c4  = (f & 15) * 4;
        float4 v = *(const float4*)&qp[row * HDIM + c4];
        float* d = &Qs[row * 65 + c4];
        d[0] = v.x * scale; d[1] = v.y * scale; d[2] = v.z * scale; d[3] = v.w * scale;
    }

    float mx[4], ls[4], o[4][4];
    #pragma unroll
    for (int i = 0; i < 4; i++) {
        mx[i] = -1e30f; ls[i] = 0.0f;
        #pragma unroll
        for (int j = 0; j < 4; j++) o[i][j] = 0.0f;
    }

    for (int t = 0; t < SEQ / 64; t++) {
        __syncthreads();   // previous iter consumers done (and Q-load on t=0)
        // Load K tile -> KP, V tile -> Vs (row-major, coalesced)
        for (int f = tid; f < 1024; f += 256) {
            const int row = f >> 4;
            const int c4  = (f & 15) * 4;
            float4 kv = *(const float4*)&kp[((size_t)t * 64 + row) * HDIM + c4];
            float* dk = &KP[row * 65 + c4];
            dk[0] = kv.x; dk[1] = kv.y; dk[2] = kv.z; dk[3] = kv.w;
            float4 vv = *(const float4*)&vp[((size_t)t * 64 + row) * HDIM + c4];
            float* dv = &Vs[row * 64 + c4];
            dv[0] = vv.x; dv[1] = vv.y; dv[2] = vv.z; dv[3] = vv.w;
        }
        __syncthreads();

        // Scores: s = (Q*scale) . K^T
        float s[4][4];
        #pragma unroll
        for (int i = 0; i < 4; i++)
            #pragma unroll
            for (int j = 0; j < 4; j++) s[i][j] = 0.0f;

        #pragma unroll 8
        for (int kk = 0; kk < 64; kk++) {
            float a[4], b[4];
            #pragma unroll
            for (int i = 0; i < 4; i++) a[i] = Qs[(4 * ty + i) * 65 + kk];
            #pragma unroll
            for (int j = 0; j < 4; j++) b[j] = KP[(4 * tx + j) * 65 + kk];
            #pragma unroll
            for (int i = 0; i < 4; i++)
                #pragma unroll
                for (int j = 0; j < 4; j++)
                    s[i][j] += a[i] * b[j];
        }

        // Online softmax (row stats across the 16 tx lanes = half-warp)
        float rs[4];
        #pragma unroll
        for (int i = 0; i < 4; i++) {
            float tm = fmaxf(fmaxf(s[i][0], s[i][1]), fmaxf(s[i][2], s[i][3]));
            #pragma unroll
            for (int off = 8; off > 0; off >>= 1)
                tm = fmaxf(tm, __shfl_xor_sync(0xffffffffu, tm, off));
            const float nm = fmaxf(mx[i], tm);
            const float corr = __expf(mx[i] - nm);
            float r = 0.0f;
            #pragma unroll
            for (int j = 0; j < 4; j++) {
                s[i][j] = __expf(s[i][j] - nm);
                r += s[i][j];
            }
            #pragma unroll
            for (int off = 8; off > 0; off >>= 1)
                r += __shfl_xor_sync(0xffffffffu, r, off);
            ls[i] = ls[i] * corr + r;
            mx[i] = nm;
            #pragma unroll
            for (int j = 0; j < 4; j++) o[i][j] *= corr;
        }

        __syncthreads();   // all threads done reading K before overwrite
        // Write P into KP
        #pragma unroll
        for (int i = 0; i < 4; i++)
            #pragma unroll
            for (int j = 0; j < 4; j++)
                KP[(4 * ty + i) * 65 + 4 * tx + j] = s[i][j];
        __syncthreads();

        // o += P . V
        #pragma unroll 8
        for (int ss = 0; ss < 64; ss++) {
            float a[4], b[4];
            #pragma unroll
            for (int i = 0; i < 4; i++) a[i] = KP[(4 * ty + i) * 65 + ss];
            #pragma unroll
            for (int j = 0; j < 4; j++) b[j] = Vs[ss * 64 + 4 * tx + j];
            #pragma unroll
            for (int i = 0; i < 4; i++)
                #pragma unroll
                for (int j = 0; j < 4; j++)
                    o[i][j] += a[i] * b[j];
        }
    }

    // Write normalized output into g_y with [b, s, h*HDIM + d] layout
    const int b = bh / NHEAD;
    const int h = bh % NHEAD;
    #pragma unroll
    for (int i = 0; i < 4; i++) {
        const float inv = 1.0f / ls[i];
        const int srow = qt * 64 + 4 * ty + i;
        float4 v = make_float4(o[i][0] * inv, o[i][1] * inv, o[i][2] * inv, o[i][3] * inv);
        *(float4*)&g_y[((size_t)(b * SEQ + srow)) * DMODEL + h * HDIM + 4 * tx] = v;
    }
}

// ----------------------------------------------------------------------------
// Launch
// ----------------------------------------------------------------------------
extern "C" void kernel_launch(void* const* d_in, const int* in_sizes, int n_in,
                              void* d_out, int out_size)
{
    const float* x  = (const float*)d_in[0];
    const float* wq = (const float*)d_in[1];
    const float* wk = (const float*)d_in[2];
    const float* wv = (const float*)d_in[3];
    const float* wo = (const float*)d_in[4];
    const float* bo = (const float*)d_in[5];
    float* out = (float*)d_out;

    dim3 blk(256);

    // 1) Fused QKV projection: grid.z = {q,k,v}
    gemm128<0><<<dim3(DMODEL / 128, MTOT / 128, 3), blk>>>(x, wq, wk, wv, nullptr, nullptr);

    // 2) Flash attention (49,664 B dynamic smem > 48K default -> opt in)
    const size_t smem = (size_t)(2 * 64 * 65 + 64 * 64) * sizeof(float);
    cudaFuncSetAttribute(attn_kernel, cudaFuncAttributeMaxDynamicSharedMemorySize, (int)smem);
    attn_kernel<<<dim3(SEQ / 64, BATCH * NHEAD), blk, smem>>>();

    // 3) Output projection + bias
    gemm128<1><<<dim3(DMODEL / 128, MTOT / 128, 1), blk>>>(nullptr, wo, nullptr, nullptr, bo, out);
}